// round 16
// baseline (speedup 1.0000x reference)
#include <cuda_runtime.h>
#include <cstdint>

// TranslateCube: out(y,x) = bilinear(in, y - ty, x - tx), zero fill.
// [B*T, 256, 256] fp32; (tx, ty) constant per image.
//
// R15: 4-buffer cp.async pipeline, DRAM 77.7%, occ 57% (reg-capped at 5
// blocks/SM). This round: __launch_bounds__(256,6) -> regs<=40 -> 6 blocks/SM.
// Unlike the R9/R13 LDG era, tighter reg caps are now safe: compute reads are
// LDS (29cyc) so de-batching them is cheap, and cp.async prefetch carries no
// register payload. 36KB smem x 6 = 216KB fits the 228KB SM budget.

#define HH 256
#define WW 256
#define TPR 32               // threads in x
#define WPB 8                // warps per block (threadIdx.y = row in tile)
#define TROWS 8              // output rows per tile
#define SROWS 9              // staged input rows per tile
#define NBUF 4
#define HALF 128             // output rows per block
#define NT (HALF / TROWS)    // 16 tiles per block
#define PDIST 3              // prefetch distance (tiles)

__device__ __forceinline__ uint32_t smem_u32(const void* p) {
    return (uint32_t)__cvta_generic_to_shared(p);
}

struct TileInfo { int y0_min, g0, lo, hi, cnt; };

__device__ __forceinline__ TileInfo tile_info(int yb, float ty) {
    TileInfo t;
    t.y0_min = (int)floorf((float)yb - ty);
    t.g0 = min(max(t.y0_min, 0), HH - 1);
    int g1 = max(min(t.y0_min + SROWS - 1, HH - 1), t.g0);
    t.lo = min(max(t.g0 - t.y0_min, 0), SROWS - 1);
    t.hi = min(max(g1   - t.y0_min, t.lo), SROWS - 1);
    t.cnt = min(g1 - t.g0 + 1, SROWS - t.lo);
    return t;
}

__device__ __forceinline__ void prefetch_tile(
    float* __restrict__ sbuf, const float* __restrict__ base,
    const TileInfo ti, int tid)
{
    const uint32_t bytes = (uint32_t)ti.cnt * (WW * 4);
    const char* src = (const char*)(base + (size_t)ti.g0 * WW);
    const uint32_t dst = smem_u32(sbuf + ti.lo * WW);
#pragma unroll
    for (int it = 0; it < (SROWS * WW * 4 + 4095) / 4096; ++it) {
        const uint32_t off = (uint32_t)tid * 16 + (uint32_t)it * 4096;
        if (off < bytes) {
            asm volatile("cp.async.cg.shared.global [%0], [%1], 16;"
                         :: "r"(dst + off), "l"(src + off) : "memory");
        }
    }
    asm volatile("cp.async.commit_group;" ::: "memory");
}

template <int M>
__device__ __forceinline__ float4 quad(
    const float4 A0, const float4 A1, const float4 B0, const float4 B1,
    const float* __restrict__ u0, const float* __restrict__ u1,
    float wtop, float wbot)
{
    const float va[8] = {A0.x, A0.y, A0.z, A0.w, A1.x, A1.y, A1.z, A1.w};
    const float vb[8] = {B0.x, B0.y, B0.z, B0.w, B1.x, B1.y, B1.z, B1.w};
    float o[4];
#pragma unroll
    for (int j = 0; j < 4; ++j) {
        const float t = fmaf(u1[j], va[M + j + 1], u0[j] * va[M + j]);
        const float s = fmaf(u1[j], vb[M + j + 1], u0[j] * vb[M + j]);
        o[j] = fmaf(wbot, s, wtop * t);
    }
    return make_float4(o[0], o[1], o[2], o[3]);
}

template <int M>
__device__ __forceinline__ void pipeline(
    const float* __restrict__ base, float4* __restrict__ obase,
    float* __restrict__ sbuf,                 // NBUF * SROWS * WW floats
    int yStart, int c, int tid,
    int ca0, int ca1, int cb0, int cb1,
    const float* __restrict__ u0a, const float* __restrict__ u1a,
    const float* __restrict__ u0b, const float* __restrict__ u1b, float ty)
{
#pragma unroll
    for (int p = 0; p < PDIST; ++p)
        prefetch_tile(sbuf + p * (SROWS * WW), base,
                      tile_info(yStart + p * TROWS, ty), tid);

    for (int t = 0; t < NT; ++t) {
        const TileInfo cur = tile_info(yStart + t * TROWS, ty);
        float* sc = sbuf + (t & (NBUF - 1)) * (SROWS * WW);

        asm volatile("cp.async.wait_group %0;" :: "n"(PDIST - 1) : "memory");
        __syncthreads();   // tile t visible to all; all finished tile t-1

        // one row per thread per tile
        const int y = yStart + t * TROWS + threadIdx.y;
        {
            const float sy  = (float)y - ty;
            const float y0f = floorf(sy);
            const float wy  = sy - y0f;
            const int   y0  = (int)y0f;
            const float wtop = ((unsigned)y0       < (unsigned)HH) ? (1.0f - wy) : 0.0f;
            const float wbot = ((unsigned)(y0 + 1) < (unsigned)HH) ? wy          : 0.0f;
            const int i0 = min(max(y0     - cur.y0_min, cur.lo), cur.hi);
            const int i1 = min(max(y0 + 1 - cur.y0_min, cur.lo), cur.hi);

            const float4* r0 = (const float4*)(sc + i0 * WW);
            const float4* r1 = (const float4*)(sc + i1 * WW);
            const float4 A0 = r0[ca0], A1 = r0[ca1], A2 = r0[cb0], A3 = r0[cb1];
            const float4 B0 = r1[ca0], B1 = r1[ca1], B2 = r1[cb0], B3 = r1[cb1];

            const float4 oA = quad<M>(A0, A1, B0, B1, u0a, u1a, wtop, wbot);
            const float4 oB = quad<M>(A2, A3, B2, B3, u0b, u1b, wtop, wbot);

            float4* dst = &obase[y * (WW / 4)];
            __stcs(dst + c,      oA);
            __stcs(dst + c + 32, oB);
        }

        // Prefetch tile t+PDIST into the buffer last read at tile t-1
        // (safe: its readers all passed this iteration's barrier).
        if (t + PDIST < NT) {
            prefetch_tile(sbuf + ((t + PDIST) & (NBUF - 1)) * (SROWS * WW),
                          base, tile_info(yStart + (t + PDIST) * TROWS, ty), tid);
        } else {
            asm volatile("cp.async.commit_group;" ::: "memory");  // empty group
        }
    }
}

__global__ __launch_bounds__(256, 6) void translate_kernel(
    const float* __restrict__ img,
    const float* __restrict__ dx,
    const float* __restrict__ dy,
    float* __restrict__ out)
{
    __shared__ __align__(16) float sbuf[NBUF * SROWS * WW];   // 36 KB

    const int bx = blockIdx.x;
    const int imgIdx = bx >> 1;
    const int yStart = (bx & 1) * HALF;

    const float tx = __ldg(dx + imgIdx);
    const float ty = __ldg(dy + imgIdx);

    const int c  = threadIdx.x;                  // 0..31
    const int xa = c * 4;
    const int xb = xa + 128;
    const int tid = threadIdx.y * TPR + threadIdx.x;

    const int x0a = (int)floorf((float)xa - tx);
    const int x0b = x0a + 128;
    const int m   = x0a & 3;                     // uniform per image
    const int qbase = (x0a - m) >> 2;

    const int ca0 = min(max(qbase,      0), WW / 4 - 1);
    const int ca1 = min(max(qbase + 1,  0), WW / 4 - 1);
    const int cb0 = min(max(qbase + 32, 0), WW / 4 - 1);
    const int cb1 = min(max(qbase + 33, 0), WW / 4 - 1);

    float u0a[4], u1a[4], u0b[4], u1b[4];
#pragma unroll
    for (int j = 0; j < 4; ++j) {
        const float wxa = ((float)(xa + j) - tx) - (float)(x0a + j);
        u0a[j] = ((unsigned)(x0a + j)     < (unsigned)WW) ? (1.0f - wxa) : 0.0f;
        u1a[j] = ((unsigned)(x0a + j + 1) < (unsigned)WW) ? wxa          : 0.0f;
        const float wxb = ((float)(xb + j) - tx) - (float)(x0b + j);
        u0b[j] = ((unsigned)(x0b + j)     < (unsigned)WW) ? (1.0f - wxb) : 0.0f;
        u1b[j] = ((unsigned)(x0b + j + 1) < (unsigned)WW) ? wxb          : 0.0f;
    }

    const float* base  = img + (size_t)imgIdx * (HH * WW);
    float4*      obase = (float4*)(out + (size_t)imgIdx * (HH * WW));

    switch (m) {
    case 0:  pipeline<0>(base, obase, sbuf, yStart, c, tid,
                         ca0, ca1, cb0, cb1, u0a, u1a, u0b, u1b, ty); break;
    case 1:  pipeline<1>(base, obase, sbuf, yStart, c, tid,
                         ca0, ca1, cb0, cb1, u0a, u1a, u0b, u1b, ty); break;
    case 2:  pipeline<2>(base, obase, sbuf, yStart, c, tid,
                         ca0, ca1, cb0, cb1, u0a, u1a, u0b, u1b, ty); break;
    default: pipeline<3>(base, obase, sbuf, yStart, c, tid,
                         ca0, ca1, cb0, cb1, u0a, u1a, u0b, u1b, ty); break;
    }
}

extern "C" void kernel_launch(void* const* d_in, const int* in_sizes, int n_in,
                              void* d_out, int out_size) {
    const float* images = (const float*)d_in[0];
    const float* dx     = (const float*)d_in[1];
    const float* dy     = (const float*)d_in[2];
    // d_in[3] is winsize (unused by the math)
    float* out = (float*)d_out;

    const int n_images = in_sizes[1];  // B*T

    dim3 block(TPR, WPB);              // 32 x 8 = 256 threads
    dim3 grid(2 * n_images);           // one block per half-image
    translate_kernel<<<grid, block>>>(images, dx, dy, out);
}

// round 17
// speedup vs baseline: 1.1348x; 1.1348x over previous
#include <cuda_runtime.h>
#include <cstdint>

// TranslateCube: out(y,x) = bilinear(in, y - ty, x - tx), zero fill.
// [B*T, 256, 256] fp32; (tx, ty) constant per image.
//
// R15 config (4-buffer cp.async pipeline, regs<=48, 5 blocks/SM) was the
// best: DRAM 77.7%, ncu 78.3us but bench 86.1us. R16 proved higher occ via
// reg-cap regresses. This round targets the bench-ncu gap (wave tail):
// one block per QUARTER image (64 rows, 8 tiles), grid 4096 -> per-block
// duration halves, so the ragged-last-wave waste halves. Steady-state
// pipeline unchanged.

#define HH 256
#define WW 256
#define TPR 32               // threads in x
#define WPB 8                // warps per block (threadIdx.y = row in tile)
#define TROWS 8              // output rows per tile
#define SROWS 9              // staged input rows per tile
#define NBUF 4
#define QROWS 64             // output rows per block (quarter image)
#define NT (QROWS / TROWS)   // 8 tiles per block
#define PDIST 3              // prefetch distance (tiles)

__device__ __forceinline__ uint32_t smem_u32(const void* p) {
    return (uint32_t)__cvta_generic_to_shared(p);
}

struct TileInfo { int y0_min, g0, lo, hi, cnt; };

__device__ __forceinline__ TileInfo tile_info(int yb, float ty) {
    TileInfo t;
    t.y0_min = (int)floorf((float)yb - ty);
    t.g0 = min(max(t.y0_min, 0), HH - 1);
    int g1 = max(min(t.y0_min + SROWS - 1, HH - 1), t.g0);
    t.lo = min(max(t.g0 - t.y0_min, 0), SROWS - 1);
    t.hi = min(max(g1   - t.y0_min, t.lo), SROWS - 1);
    t.cnt = min(g1 - t.g0 + 1, SROWS - t.lo);
    return t;
}

__device__ __forceinline__ void prefetch_tile(
    float* __restrict__ sbuf, const float* __restrict__ base,
    const TileInfo ti, int tid)
{
    const uint32_t bytes = (uint32_t)ti.cnt * (WW * 4);
    const char* src = (const char*)(base + (size_t)ti.g0 * WW);
    const uint32_t dst = smem_u32(sbuf + ti.lo * WW);
#pragma unroll
    for (int it = 0; it < (SROWS * WW * 4 + 4095) / 4096; ++it) {
        const uint32_t off = (uint32_t)tid * 16 + (uint32_t)it * 4096;
        if (off < bytes) {
            asm volatile("cp.async.cg.shared.global [%0], [%1], 16;"
                         :: "r"(dst + off), "l"(src + off) : "memory");
        }
    }
    asm volatile("cp.async.commit_group;" ::: "memory");
}

template <int M>
__device__ __forceinline__ float4 quad(
    const float4 A0, const float4 A1, const float4 B0, const float4 B1,
    const float* __restrict__ u0, const float* __restrict__ u1,
    float wtop, float wbot)
{
    const float va[8] = {A0.x, A0.y, A0.z, A0.w, A1.x, A1.y, A1.z, A1.w};
    const float vb[8] = {B0.x, B0.y, B0.z, B0.w, B1.x, B1.y, B1.z, B1.w};
    float o[4];
#pragma unroll
    for (int j = 0; j < 4; ++j) {
        const float t = fmaf(u1[j], va[M + j + 1], u0[j] * va[M + j]);
        const float s = fmaf(u1[j], vb[M + j + 1], u0[j] * vb[M + j]);
        o[j] = fmaf(wbot, s, wtop * t);
    }
    return make_float4(o[0], o[1], o[2], o[3]);
}

template <int M>
__device__ __forceinline__ void pipeline(
    const float* __restrict__ base, float4* __restrict__ obase,
    float* __restrict__ sbuf,                 // NBUF * SROWS * WW floats
    int yStart, int c, int tid,
    int ca0, int ca1, int cb0, int cb1,
    const float* __restrict__ u0a, const float* __restrict__ u1a,
    const float* __restrict__ u0b, const float* __restrict__ u1b, float ty)
{
#pragma unroll
    for (int p = 0; p < PDIST; ++p)
        prefetch_tile(sbuf + p * (SROWS * WW), base,
                      tile_info(yStart + p * TROWS, ty), tid);

    for (int t = 0; t < NT; ++t) {
        const TileInfo cur = tile_info(yStart + t * TROWS, ty);
        float* sc = sbuf + (t & (NBUF - 1)) * (SROWS * WW);

        asm volatile("cp.async.wait_group %0;" :: "n"(PDIST - 1) : "memory");
        __syncthreads();   // tile t visible to all; all finished tile t-1

        // one row per thread per tile
        const int y = yStart + t * TROWS + threadIdx.y;
        {
            const float sy  = (float)y - ty;
            const float y0f = floorf(sy);
            const float wy  = sy - y0f;
            const int   y0  = (int)y0f;
            const float wtop = ((unsigned)y0       < (unsigned)HH) ? (1.0f - wy) : 0.0f;
            const float wbot = ((unsigned)(y0 + 1) < (unsigned)HH) ? wy          : 0.0f;
            const int i0 = min(max(y0     - cur.y0_min, cur.lo), cur.hi);
            const int i1 = min(max(y0 + 1 - cur.y0_min, cur.lo), cur.hi);

            const float4* r0 = (const float4*)(sc + i0 * WW);
            const float4* r1 = (const float4*)(sc + i1 * WW);
            const float4 A0 = r0[ca0], A1 = r0[ca1], A2 = r0[cb0], A3 = r0[cb1];
            const float4 B0 = r1[ca0], B1 = r1[ca1], B2 = r1[cb0], B3 = r1[cb1];

            const float4 oA = quad<M>(A0, A1, B0, B1, u0a, u1a, wtop, wbot);
            const float4 oB = quad<M>(A2, A3, B2, B3, u0b, u1b, wtop, wbot);

            float4* dst = &obase[y * (WW / 4)];
            __stcs(dst + c,      oA);
            __stcs(dst + c + 32, oB);
        }

        // Prefetch tile t+PDIST into the buffer last read at tile t-1
        // (safe: its readers all passed this iteration's barrier).
        if (t + PDIST < NT) {
            prefetch_tile(sbuf + ((t + PDIST) & (NBUF - 1)) * (SROWS * WW),
                          base, tile_info(yStart + (t + PDIST) * TROWS, ty), tid);
        } else {
            asm volatile("cp.async.commit_group;" ::: "memory");  // empty group
        }
    }
}

__global__ __launch_bounds__(256, 5) void translate_kernel(
    const float* __restrict__ img,
    const float* __restrict__ dx,
    const float* __restrict__ dy,
    float* __restrict__ out)
{
    __shared__ __align__(16) float sbuf[NBUF * SROWS * WW];   // 36 KB

    const int bx = blockIdx.x;
    const int imgIdx = bx >> 2;
    const int yStart = (bx & 3) * QROWS;

    const float tx = __ldg(dx + imgIdx);
    const float ty = __ldg(dy + imgIdx);

    const int c  = threadIdx.x;                  // 0..31
    const int xa = c * 4;
    const int xb = xa + 128;
    const int tid = threadIdx.y * TPR + threadIdx.x;

    const int x0a = (int)floorf((float)xa - tx);
    const int x0b = x0a + 128;
    const int m   = x0a & 3;                     // uniform per image
    const int qbase = (x0a - m) >> 2;

    const int ca0 = min(max(qbase,      0), WW / 4 - 1);
    const int ca1 = min(max(qbase + 1,  0), WW / 4 - 1);
    const int cb0 = min(max(qbase + 32, 0), WW / 4 - 1);
    const int cb1 = min(max(qbase + 33, 0), WW / 4 - 1);

    float u0a[4], u1a[4], u0b[4], u1b[4];
#pragma unroll
    for (int j = 0; j < 4; ++j) {
        const float wxa = ((float)(xa + j) - tx) - (float)(x0a + j);
        u0a[j] = ((unsigned)(x0a + j)     < (unsigned)WW) ? (1.0f - wxa) : 0.0f;
        u1a[j] = ((unsigned)(x0a + j + 1) < (unsigned)WW) ? wxa          : 0.0f;
        const float wxb = ((float)(xb + j) - tx) - (float)(x0b + j);
        u0b[j] = ((unsigned)(x0b + j)     < (unsigned)WW) ? (1.0f - wxb) : 0.0f;
        u1b[j] = ((unsigned)(x0b + j + 1) < (unsigned)WW) ? wxb          : 0.0f;
    }

    const float* base  = img + (size_t)imgIdx * (HH * WW);
    float4*      obase = (float4*)(out + (size_t)imgIdx * (HH * WW));

    switch (m) {
    case 0:  pipeline<0>(base, obase, sbuf, yStart, c, tid,
                         ca0, ca1, cb0, cb1, u0a, u1a, u0b, u1b, ty); break;
    case 1:  pipeline<1>(base, obase, sbuf, yStart, c, tid,
                         ca0, ca1, cb0, cb1, u0a, u1a, u0b, u1b, ty); break;
    case 2:  pipeline<2>(base, obase, sbuf, yStart, c, tid,
                         ca0, ca1, cb0, cb1, u0a, u1a, u0b, u1b, ty); break;
    default: pipeline<3>(base, obase, sbuf, yStart, c, tid,
                         ca0, ca1, cb0, cb1, u0a, u1a, u0b, u1b, ty); break;
    }
}

extern "C" void kernel_launch(void* const* d_in, const int* in_sizes, int n_in,
                              void* d_out, int out_size) {
    const float* images = (const float*)d_in[0];
    const float* dx     = (const float*)d_in[1];
    const float* dy     = (const float*)d_in[2];
    // d_in[3] is winsize (unused by the math)
    float* out = (float*)d_out;

    const int n_images = in_sizes[1];  // B*T

    dim3 block(TPR, WPB);              // 32 x 8 = 256 threads
    dim3 grid(4 * n_images);           // one block per quarter image
    translate_kernel<<<grid, block>>>(images, dx, dy, out);
}